// round 13
// baseline (speedup 1.0000x reference)
#include <cuda_runtime.h>
#include <cuda_bf16.h>
#include <cstdint>
#include <cstddef>

// Problem constants
#define NN 100000      // nodes
#define NE 800000      // edges
#define HD 256         // hidden dim
#define NL 6           // layers
#define W1_LD 259      // H + 3 edge features
#define W2_LD 512      // H + INTER
#define HP 128         // packed pairs per node row (HD/2)

// ---------------- scratch (device globals; no runtime allocation) ----------
__device__ float g_P [(size_t)NN * HD];
__device__ uint2 g_hPkA[(size_t)NN * HP];
__device__ uint2 g_hPkB[(size_t)NN * HP];
__device__ uint2 g_hNp [(size_t)NN * HP];
__device__ uint2 g_W1p [NL * 256 * 128];
__device__ uint2 g_W2p [NL * 256 * 256];
__device__ uint2 g_Wh1p[256 * 128];
__device__ int   g_offs[NN + 1];
__device__ int   g_cursor[NN];
__device__ int   g_eidx[NE];
__device__ int   g_bsum[256];

// split a,b into bf16 (hi, lo) packed words
__device__ __forceinline__ void split2(float a, float b, uint32_t& hi, uint32_t& lo) {
    __nv_bfloat16 ha = __float2bfloat16(a);
    __nv_bfloat16 hb = __float2bfloat16(b);
    __nv_bfloat16 la = __float2bfloat16(a - __bfloat162float(ha));
    __nv_bfloat16 lb = __float2bfloat16(b - __bfloat162float(hb));
    __nv_bfloat162 h2 = __halves2bfloat162(ha, hb);
    __nv_bfloat162 l2 = __halves2bfloat162(la, lb);
    hi = *reinterpret_cast<uint32_t*>(&h2);
    lo = *reinterpret_cast<uint32_t*>(&l2);
}

__device__ __forceinline__ void mma_bf16(float* c,
                                         uint32_t a0, uint32_t a1, uint32_t a2, uint32_t a3,
                                         uint32_t b0, uint32_t b1) {
    asm volatile(
        "mma.sync.aligned.m16n8k16.row.col.f32.bf16.bf16.f32 "
        "{%0,%1,%2,%3}, {%4,%5,%6,%7}, {%8,%9}, {%0,%1,%2,%3};"
        : "+f"(c[0]), "+f"(c[1]), "+f"(c[2]), "+f"(c[3])
        : "r"(a0), "r"(a1), "r"(a2), "r"(a3), "r"(b0), "r"(b1));
}

__device__ __forceinline__ void cp_async16(uint32_t smem_dst, const void* gsrc) {
    asm volatile("cp.async.cg.shared.global [%0], [%1], 16;"
                 :: "r"(smem_dst), "l"(gsrc) : "memory");
}
#define CP_COMMIT() asm volatile("cp.async.commit_group;" ::: "memory")
#define CP_WAIT0()  asm volatile("cp.async.wait_group 0;" ::: "memory")

// ---------------- setup kernels --------------------------------------------
__global__ void init_kernel(const int* __restrict__ gt,
                            const float* __restrict__ emb,
                            uint2* __restrict__ hp) {
    int i = blockIdx.x * blockDim.x + threadIdx.x;
    if (i < NN * HP) {
        int node = i >> 7;
        int j    = i & 127;
        const float* e = emb + gt[node] * HD + 2 * j;
        uint32_t hi, lo;
        split2(e[0], e[1], hi, lo);
        hp[i] = make_uint2(hi, lo);
    }
}

__global__ void zero_int(int* __restrict__ p, int n) {
    int i = blockIdx.x * blockDim.x + threadIdx.x;
    if (i < n) p[i] = 0;
}

__global__ void count_kernel(const int* __restrict__ dst, int* __restrict__ ideg) {
    int e = blockIdx.x * blockDim.x + threadIdx.x;
    if (e < NE) atomicAdd(&ideg[dst[e]], 1);
}

#define SB 512
__global__ void scan_block(const int* __restrict__ in, int* __restrict__ outEx,
                           int* __restrict__ bsum, int n) {
    __shared__ int s[SB];
    int i = blockIdx.x * SB + threadIdx.x;
    int v = (i < n) ? in[i] : 0;
    s[threadIdx.x] = v;
    __syncthreads();
    for (int d = 1; d < SB; d <<= 1) {
        int t = (threadIdx.x >= (unsigned)d) ? s[threadIdx.x - d] : 0;
        __syncthreads();
        s[threadIdx.x] += t;
        __syncthreads();
    }
    if (i < n) outEx[i] = s[threadIdx.x] - v;
    if (threadIdx.x == SB - 1) bsum[blockIdx.x] = s[SB - 1];
}

__global__ void scan_tops(int* __restrict__ bsum, int nb) {
    __shared__ int s[SB];
    int v = (threadIdx.x < (unsigned)nb) ? bsum[threadIdx.x] : 0;
    s[threadIdx.x] = v;
    __syncthreads();
    for (int d = 1; d < SB; d <<= 1) {
        int t = (threadIdx.x >= (unsigned)d) ? s[threadIdx.x - d] : 0;
        __syncthreads();
        s[threadIdx.x] += t;
        __syncthreads();
    }
    if (threadIdx.x < (unsigned)nb) bsum[threadIdx.x] = s[threadIdx.x] - v;
}

__global__ void scan_add(int* __restrict__ outEx, const int* __restrict__ bsum,
                         int* __restrict__ cursor, int n) {
    int i = blockIdx.x * blockDim.x + threadIdx.x;
    if (i < n) {
        int v = outEx[i] + bsum[i / SB];
        outEx[i] = v;
        cursor[i] = v;
    }
    if (i == 0) outEx[n] = NE;
}

__global__ void fill_kernel(const int* __restrict__ dst, int* __restrict__ cursor,
                            int* __restrict__ eidx) {
    int e = blockIdx.x * blockDim.x + threadIdx.x;
    if (e < NE) {
        int pos = atomicAdd(&cursor[dst[e]], 1);
        eidx[pos] = e;
    }
}

// pack fp32 [rows, srcld] -> uint2 hi/lo [rows, kp]
__global__ void pack_kernel(const float* __restrict__ src, int srcld, int kp,
                            int total, uint2* __restrict__ dst) {
    int i = blockIdx.x * blockDim.x + threadIdx.x;
    if (i >= total) return;
    int r = i / kp, j = i - r * kp;
    float a = src[(size_t)r * srcld + 2 * j];
    float b = src[(size_t)r * srcld + 2 * j + 1];
    uint32_t hi, lo;
    split2(a, b, hi, lo);
    dst[(size_t)r * kp + j] = make_uint2(hi, lo);
}

// ---------------- CSR gather-reduce: hNp[n] = pack(mean_e leaky(P[src]+w@W1b)) ----
__global__ void csr_edge_kernel(const int* __restrict__ offs,
                                const int* __restrict__ eidx,
                                const int* __restrict__ src,
                                const float* __restrict__ w,
                                const float* __restrict__ P,
                                const float* __restrict__ W1b,
                                uint2* __restrict__ hNp) {
    __shared__ float sW[3 * HD];
    for (int i = threadIdx.x; i < HD; i += blockDim.x) {
        sW[i]          = W1b[(size_t)i * W1_LD + 0];
        sW[HD + i]     = W1b[(size_t)i * W1_LD + 1];
        sW[2 * HD + i] = W1b[(size_t)i * W1_LD + 2];
    }
    __syncthreads();

    int node = blockIdx.x * (blockDim.x >> 5) + (threadIdx.x >> 5);
    int lane = threadIdx.x & 31;
    if (node >= NN) return;

    int beg = offs[node], end = offs[node + 1];
    int c0 = lane * 4;
    int c1 = 128 + lane * 4;

    float w00 = sW[c0], w01 = sW[c0+1], w02 = sW[c0+2], w03 = sW[c0+3];
    float w10 = sW[HD+c0], w11 = sW[HD+c0+1], w12 = sW[HD+c0+2], w13 = sW[HD+c0+3];
    float w20 = sW[2*HD+c0], w21 = sW[2*HD+c0+1], w22 = sW[2*HD+c0+2], w23 = sW[2*HD+c0+3];
    float v00 = sW[c1], v01 = sW[c1+1], v02 = sW[c1+2], v03 = sW[c1+3];
    float v10 = sW[HD+c1], v11 = sW[HD+c1+1], v12 = sW[HD+c1+2], v13 = sW[HD+c1+3];
    float v20 = sW[2*HD+c1], v21 = sW[2*HD+c1+1], v22 = sW[2*HD+c1+2], v23 = sW[2*HD+c1+3];

    float acc[8];
#pragma unroll
    for (int i = 0; i < 8; i++) acc[i] = 0.0f;

    for (int e = beg; e < end; e++) {
        int ed = eidx[e];
        int s  = src[ed];
        float e0 = w[ed * 3 + 0];
        float e1 = w[ed * 3 + 1];
        float e2 = w[ed * 3 + 2];
        const float* Ps = P + (size_t)s * HD;
        float4 p0 = *(const float4*)(Ps + c0);
        float4 p1 = *(const float4*)(Ps + c1);
        float t;
        t = p0.x + e0*w00 + e1*w10 + e2*w20; acc[0] += t > 0.f ? t : 0.01f*t;
        t = p0.y + e0*w01 + e1*w11 + e2*w21; acc[1] += t > 0.f ? t : 0.01f*t;
        t = p0.z + e0*w02 + e1*w12 + e2*w22; acc[2] += t > 0.f ? t : 0.01f*t;
        t = p0.w + e0*w03 + e1*w13 + e2*w23; acc[3] += t > 0.f ? t : 0.01f*t;
        t = p1.x + e0*v00 + e1*v10 + e2*v20; acc[4] += t > 0.f ? t : 0.01f*t;
        t = p1.y + e0*v01 + e1*v11 + e2*v21; acc[5] += t > 0.f ? t : 0.01f*t;
        t = p1.z + e0*v02 + e1*v12 + e2*v22; acc[6] += t > 0.f ? t : 0.01f*t;
        t = p1.w + e0*v03 + e1*v13 + e2*v23; acc[7] += t > 0.f ? t : 0.01f*t;
    }

    float inv = 1.0f / fmaxf((float)(end - beg), 1.0f);
#pragma unroll
    for (int i = 0; i < 8; i++) acc[i] *= inv;

    uint2* outp = hNp + (size_t)node * HP;
    uint32_t hi, lo;
    split2(acc[0], acc[1], hi, lo); outp[lane * 2]          = make_uint2(hi, lo);
    split2(acc[2], acc[3], hi, lo); outp[lane * 2 + 1]      = make_uint2(hi, lo);
    split2(acc[4], acc[5], hi, lo); outp[64 + lane * 2]     = make_uint2(hi, lo);
    split2(acc[6], acc[7], hi, lo); outp[64 + lane * 2 + 1] = make_uint2(hi, lo);
}

// ---------------- tensor-core bf16 GEMM: packed operands + cp.async pipe ---
#define BM 128
#define BN 64
#define KC 32
#define RW 32   // 32-bit words per row

__global__ __launch_bounds__(256, 3)
void mma_gemm_kernel(const uint2* __restrict__ A1, int K1,
                     const uint2* __restrict__ A2, int K2,
                     const uint2* __restrict__ Bp,
                     const float* __restrict__ bias,
                     float* __restrict__ C, uint2* __restrict__ Cp,
                     int M, int N, int act) {
    __shared__ uint32_t Aw[2][BM * RW];   // 2 x 16 KB
    __shared__ uint32_t Bw[2][BN * RW];   // 2 x  8 KB

    int tid  = threadIdx.x;
    int wid  = tid >> 5;
    int lane = tid & 31;
    int grp  = lane >> 2;
    int tg   = lane & 3;
    int warp_m = wid & 3;
    int warp_n = wid >> 2;
    int m0 = warp_m * 32;
    int n0 = warp_n * 32;
    int mBase = blockIdx.y * BM;
    int nBase = blockIdx.x * BN;

    int K = K1 + K2;
    int nch = K / KC;
    int k1ch = K1 / KC;
    int kpB = K >> 1;

    uint32_t aSm[2], bSm[2];
    aSm[0] = (uint32_t)__cvta_generic_to_shared(&Aw[0][0]);
    aSm[1] = (uint32_t)__cvta_generic_to_shared(&Aw[1][0]);
    bSm[0] = (uint32_t)__cvta_generic_to_shared(&Bw[0][0]);
    bSm[1] = (uint32_t)__cvta_generic_to_shared(&Bw[1][0]);

    float acc[2][4][4];
#pragma unroll
    for (int i = 0; i < 2; i++)
#pragma unroll
        for (int j = 0; j < 4; j++)
#pragma unroll
            for (int q = 0; q < 4; q++) acc[i][j][q] = 0.0f;

    auto load_chunk = [&](int kc, int b) {
        int kp = kc * (KC / 2);
        bool u2 = (kc >= k1ch);
        const uint2* Ap = u2 ? A2 : A1;
        int kpa = u2 ? kp - (K1 >> 1) : kp;
        int lda = (u2 ? K2 : K1) >> 1;
#pragma unroll
        for (int i = 0; i < 4; i++) {
            int job = tid + i * 256;
            int r = job >> 3, s = job & 7;
            int row = mBase + r; if (row >= M) row = M - 1;
            const uint2* g = Ap + (size_t)row * lda + kpa + 2 * s;
            uint32_t d = aSm[b] + (uint32_t)(r * RW + ((4 * s) ^ ((r & 3) << 3))) * 4u;
            cp_async16(d, g);
        }
#pragma unroll
        for (int i = 0; i < 2; i++) {
            int job = tid + i * 256;
            int r = job >> 3, s = job & 7;
            const uint2* g = Bp + (size_t)(nBase + r) * kpB + kp + 2 * s;
            uint32_t d = bSm[b] + (uint32_t)(r * RW + ((4 * s) ^ ((r & 3) << 3))) * 4u;
            cp_async16(d, g);
        }
    };

    load_chunk(0, 0);
    CP_COMMIT();

    for (int kc = 0; kc < nch; kc++) {
        int b = kc & 1;
        CP_WAIT0();
        __syncthreads();
        if (kc + 1 < nch) { load_chunk(kc + 1, (kc + 1) & 1); CP_COMMIT(); }

        const uint32_t* A = Aw[b];
        const uint32_t* Bs = Bw[b];
#pragma unroll
        for (int ks = 0; ks < 2; ks++) {
            uint2 aF[2][4];
#pragma unroll
            for (int mt = 0; mt < 2; mt++) {
                int r = m0 + mt * 16 + grp;
                int sw = (r & 3) << 2;
                int p0 = (ks * 8 + tg) ^ sw;
                int p1 = (ks * 8 + tg + 4) ^ sw;
                aF[mt][0] = *(const uint2*)&A[r * RW + 2 * p0];
                aF[mt][1] = *(const uint2*)&A[(r + 8) * RW + 2 * p0];
                aF[mt][2] = *(const uint2*)&A[r * RW + 2 * p1];
                aF[mt][3] = *(const uint2*)&A[(r + 8) * RW + 2 * p1];
            }
            uint2 bF[4][2];
#pragma unroll
            for (int nt = 0; nt < 4; nt++) {
                int nr = n0 + nt * 8 + grp;
                int sw = (nr & 3) << 2;
                bF[nt][0] = *(const uint2*)&Bs[nr * RW + 2 * ((ks * 8 + tg) ^ sw)];
                bF[nt][1] = *(const uint2*)&Bs[nr * RW + 2 * ((ks * 8 + tg + 4) ^ sw)];
            }
#pragma unroll
            for (int mt = 0; mt < 2; mt++)
#pragma unroll
                for (int nt = 0; nt < 4; nt++) {
                    float* c = acc[mt][nt];
                    mma_bf16(c, aF[mt][0].x, aF[mt][1].x, aF[mt][2].x, aF[mt][3].x,
                             bF[nt][0].x, bF[nt][1].x);
                    mma_bf16(c, aF[mt][0].y, aF[mt][1].y, aF[mt][2].y, aF[mt][3].y,
                             bF[nt][0].x, bF[nt][1].x);
                    mma_bf16(c, aF[mt][0].x, aF[mt][1].x, aF[mt][2].x, aF[mt][3].x,
                             bF[nt][0].y, bF[nt][1].y);
                }
        }
        __syncthreads();
    }

#pragma unroll
    for (int mt = 0; mt < 2; mt++) {
#pragma unroll
        for (int half = 0; half < 2; half++) {
            int row = mBase + m0 + mt * 16 + grp + half * 8;
            if (row >= M) continue;
#pragma unroll
            for (int nt = 0; nt < 4; nt++) {
                int col = nBase + n0 + nt * 8 + 2 * tg;
                float2 v;
                v.x = acc[mt][nt][half * 2 + 0];
                v.y = acc[mt][nt][half * 2 + 1];
                if (bias) { v.x += bias[col]; v.y += bias[col + 1]; }
                if (act)  { v.x = fmaxf(v.x, 0.0f); v.y = fmaxf(v.y, 0.0f); }
                if (Cp) {
                    uint32_t hi, lo;
                    split2(v.x, v.y, hi, lo);
                    Cp[(size_t)row * (N >> 1) + (col >> 1)] = make_uint2(hi, lo);
                } else {
                    *(float2*)(C + (size_t)row * N + col) = v;
                }
            }
        }
    }
}

// ---------------- head dot: out[n] = x[n] . Wh2 + bh2 ----------------------
__global__ void head_dot_kernel(const float* __restrict__ x,
                                const float* __restrict__ Wh2,
                                const float* __restrict__ bh2,
                                float* __restrict__ out) {
    int node = blockIdx.x * (blockDim.x >> 5) + (threadIdx.x >> 5);
    int lane = threadIdx.x & 31;
    if (node >= NN) return;
    const float* xr = x + (size_t)node * HD;
    float s = 0.0f;
#pragma unroll
    for (int j = 0; j < 8; j++) {
        int c = lane + j * 32;
        s = fmaf(xr[c], Wh2[c], s);
    }
#pragma unroll
    for (int off = 16; off; off >>= 1)
        s += __shfl_xor_sync(0xffffffffu, s, off);
    if (lane == 0) out[node] = s + bh2[0];
}

// ---------------- launch ---------------------------------------------------
extern "C" void kernel_launch(void* const* d_in, const int* in_sizes, int n_in,
                              void* d_out, int out_size) {
    const int*   gate_type = (const int*)  d_in[0];
    const int*   src       = (const int*)  d_in[1];
    const int*   dst       = (const int*)  d_in[2];
    const float* w         = (const float*)d_in[3];
    const float* emb       = (const float*)d_in[4];
    const float* W1        = (const float*)d_in[5];
    const float* W2        = (const float*)d_in[6];
    const float* b2        = (const float*)d_in[7];
    const float* Wh1       = (const float*)d_in[8];
    const float* bh1       = (const float*)d_in[9];
    const float* Wh2       = (const float*)d_in[10];
    const float* bh2       = (const float*)d_in[11];
    float* out = (float*)d_out;

    float *P;
    uint2 *hPkA, *hPkB, *hNp, *W1p, *W2p, *Wh1p;
    int *offs, *cursor, *eidx, *bsum;
    cudaGetSymbolAddress((void**)&P,      g_P);
    cudaGetSymbolAddress((void**)&hPkA,   g_hPkA);
    cudaGetSymbolAddress((void**)&hPkB,   g_hPkB);
    cudaGetSymbolAddress((void**)&hNp,    g_hNp);
    cudaGetSymbolAddress((void**)&W1p,    g_W1p);
    cudaGetSymbolAddress((void**)&W2p,    g_W2p);
    cudaGetSymbolAddress((void**)&Wh1p,   g_Wh1p);
    cudaGetSymbolAddress((void**)&offs,   g_offs);
    cudaGetSymbolAddress((void**)&cursor, g_cursor);
    cudaGetSymbolAddress((void**)&eidx,   g_eidx);
    cudaGetSymbolAddress((void**)&bsum,   g_bsum);

    // h0 packed
    init_kernel<<<(NN * HP + 255) / 256, 256>>>(gate_type, emb, hPkA);

    // CSR build (graph static across layers)
    int nb = (NN + SB - 1) / SB;   // 196
    zero_int<<<(NN + 255) / 256, 256>>>(cursor, NN);   // cursor as ideg first
    count_kernel<<<(NE + 255) / 256, 256>>>(dst, cursor);
    scan_block<<<nb, SB>>>(cursor, offs, bsum, NN);
    scan_tops<<<1, SB>>>(bsum, nb);
    scan_add<<<(NN + 255) / 256, 256>>>(offs, bsum, cursor, NN);
    fill_kernel<<<(NE + 255) / 256, 256>>>(dst, cursor, eidx);

    // pack weights (once per launch)
    for (int l = 0; l < NL; l++) {
        pack_kernel<<<(256 * 128 + 255) / 256, 256>>>(
            W1 + (size_t)l * HD * W1_LD, W1_LD, 128, 256 * 128,
            W1p + (size_t)l * 256 * 128);
        pack_kernel<<<(256 * 256 + 255) / 256, 256>>>(
            W2 + (size_t)l * HD * W2_LD, W2_LD, 256, 256 * 256,
            W2p + (size_t)l * 256 * 256);
    }
    pack_kernel<<<(256 * 128 + 255) / 256, 256>>>(Wh1, HD, 128, 256 * 128, Wh1p);

    dim3 ggrid(HD / BN, (NN + BM - 1) / BM);   // (4, 782)
    uint2* hcur = hPkA;
    uint2* hnext = hPkB;

    for (int l = 0; l < NL; l++) {
        const float* W1l = W1 + (size_t)l * HD * W1_LD;
        const float* b2l = b2 + (size_t)l * HD;

        // P = h @ W1[:, :256]^T  (fp32 out, consumed by edge gather)
        mma_gemm_kernel<<<ggrid, 256>>>(hcur, HD, nullptr, 0,
                                        W1p + (size_t)l * 256 * 128,
                                        nullptr, P, nullptr, NN, HD, 0);

        // hNp[n] = pack(mean over in-edges of leaky(P[src] + w@W1b^T))
        csr_edge_kernel<<<(NN * 32 + 255) / 256, 256>>>(offs, eidx, src, w, P,
                                                        W1l + HD, hNp);

        // h' = relu([h | hNp] @ W2^T + b2) -> packed
        mma_gemm_kernel<<<ggrid, 256>>>(hcur, HD, hNp, HD,
                                        W2p + (size_t)l * 256 * 256,
                                        b2l, nullptr, hnext, NN, HD, 1);

        uint2* t = hcur; hcur = hnext; hnext = t;
    }

    // head: x = relu(h @ Wh1^T + bh1) (fp32); out = x @ Wh2^T + bh2
    mma_gemm_kernel<<<ggrid, 256>>>(hcur, HD, nullptr, 0, Wh1p,
                                    bh1, P, nullptr, NN, HD, 1);
    head_dot_kernel<<<(NN * 32 + 255) / 256, 256>>>(P, Wh2, bh2, out);
}

// round 14
// speedup vs baseline: 1.3114x; 1.3114x over previous
#include <cuda_runtime.h>
#include <cuda_bf16.h>
#include <cstdint>
#include <cstddef>

// Problem constants
#define NN 100000      // nodes
#define NE 800000      // edges
#define HD 256         // hidden dim
#define NL 6           // layers
#define W1_LD 259      // H + 3 edge features
#define W2_LD 512      // H + INTER
#define HP 128         // packed pairs per node row (HD/2)

// ---------------- scratch (device globals; no runtime allocation) ----------
__device__ float g_P [(size_t)NN * HD];
__device__ float g_hN[(size_t)NN * HD];
__device__ float g_deg[NN];
__device__ float g_invdeg[NN];
__device__ uint2 g_hPkA[(size_t)NN * HP];
__device__ uint2 g_hPkB[(size_t)NN * HP];
__device__ uint2 g_hNp [(size_t)NN * HP];
__device__ uint2 g_W1p [NL * 256 * 128];
__device__ uint2 g_W2p [NL * 256 * 256];
__device__ uint2 g_Wh1p[256 * 128];

// split a,b into bf16 (hi, lo) packed words
__device__ __forceinline__ void split2(float a, float b, uint32_t& hi, uint32_t& lo) {
    __nv_bfloat16 ha = __float2bfloat16(a);
    __nv_bfloat16 hb = __float2bfloat16(b);
    __nv_bfloat16 la = __float2bfloat16(a - __bfloat162float(ha));
    __nv_bfloat16 lb = __float2bfloat16(b - __bfloat162float(hb));
    __nv_bfloat162 h2 = __halves2bfloat162(ha, hb);
    __nv_bfloat162 l2 = __halves2bfloat162(la, lb);
    hi = *reinterpret_cast<uint32_t*>(&h2);
    lo = *reinterpret_cast<uint32_t*>(&l2);
}

__device__ __forceinline__ void mma_bf16(float* c,
                                         uint32_t a0, uint32_t a1, uint32_t a2, uint32_t a3,
                                         uint32_t b0, uint32_t b1) {
    asm volatile(
        "mma.sync.aligned.m16n8k16.row.col.f32.bf16.bf16.f32 "
        "{%0,%1,%2,%3}, {%4,%5,%6,%7}, {%8,%9}, {%0,%1,%2,%3};"
        : "+f"(c[0]), "+f"(c[1]), "+f"(c[2]), "+f"(c[3])
        : "r"(a0), "r"(a1), "r"(a2), "r"(a3), "r"(b0), "r"(b1));
}

__device__ __forceinline__ void cp_async16(uint32_t smem_dst, const void* gsrc) {
    asm volatile("cp.async.cg.shared.global [%0], [%1], 16;"
                 :: "r"(smem_dst), "l"(gsrc) : "memory");
}
#define CP_COMMIT() asm volatile("cp.async.commit_group;" ::: "memory")
#define CP_WAIT0()  asm volatile("cp.async.wait_group 0;" ::: "memory")

// ---------------- small elementwise kernels --------------------------------
__global__ void init_kernel(const int* __restrict__ gt,
                            const float* __restrict__ emb,
                            uint2* __restrict__ hp,
                            float* __restrict__ deg,
                            float* __restrict__ outv,
                            const float* __restrict__ bh2) {
    int i = blockIdx.x * blockDim.x + threadIdx.x;
    if (i < NN * HP) {
        int node = i >> 7;
        int j    = i & 127;
        const float* e = emb + gt[node] * HD + 2 * j;
        uint32_t hi, lo;
        split2(e[0], e[1], hi, lo);
        hp[i] = make_uint2(hi, lo);
    }
    if (i < NN) {
        deg[i] = 0.0f;
        outv[i] = bh2[0];     // out pre-initialized for fused head dot
    }
}

__global__ void deg_kernel(const int* __restrict__ dst, float* __restrict__ deg) {
    int e = blockIdx.x * blockDim.x + threadIdx.x;
    if (e < NE) atomicAdd(&deg[dst[e]], 1.0f);
}

__global__ void invdeg_kernel(const float* __restrict__ deg, float* __restrict__ inv) {
    int i = blockIdx.x * blockDim.x + threadIdx.x;
    if (i < NN) inv[i] = 1.0f / fmaxf(deg[i], 1.0f);
}

__global__ void zero_kernel(float4* __restrict__ p, int n4) {
    int i = blockIdx.x * blockDim.x + threadIdx.x;
    int stride = gridDim.x * blockDim.x;
    float4 z = make_float4(0.f, 0.f, 0.f, 0.f);
    for (; i < n4; i += stride) p[i] = z;
}

// pack fp32 [rows, srcld] -> uint2 hi/lo [rows, kp], optional per-row scale;
// optionally zero the source in the same pass (fused zero for next layer)
__global__ void pack_kernel(float* __restrict__ src, int srcld, int kp,
                            int total, const float* __restrict__ rowscale,
                            uint2* __restrict__ dst, int zero_src) {
    int i = blockIdx.x * blockDim.x + threadIdx.x;
    if (i >= total) return;
    int r = i / kp, j = i - r * kp;
    float a = src[(size_t)r * srcld + 2 * j];
    float b = src[(size_t)r * srcld + 2 * j + 1];
    if (rowscale) { float s = rowscale[r]; a *= s; b *= s; }
    uint32_t hi, lo;
    split2(a, b, hi, lo);
    dst[(size_t)r * kp + j] = make_uint2(hi, lo);
    if (zero_src) {
        src[(size_t)r * srcld + 2 * j]     = 0.0f;
        src[(size_t)r * srcld + 2 * j + 1] = 0.0f;
    }
}

// ---------------- edge scatter: hN[dst] += leaky_relu(P[src] + w@W1b^T) ----
__global__ void edge_kernel(const int* __restrict__ src,
                            const int* __restrict__ dst,
                            const float* __restrict__ w,
                            const float* __restrict__ P,
                            const float* __restrict__ W1b,  // points at W1[l][0][256]
                            float* __restrict__ hN) {
    __shared__ float sW[3 * HD];
    for (int i = threadIdx.x; i < HD; i += blockDim.x) {
        sW[i]          = W1b[(size_t)i * W1_LD + 0];
        sW[HD + i]     = W1b[(size_t)i * W1_LD + 1];
        sW[2 * HD + i] = W1b[(size_t)i * W1_LD + 2];
    }
    __syncthreads();

    int warpId = (blockIdx.x * blockDim.x + threadIdx.x) >> 5;
    int lane   = threadIdx.x & 31;
    if (warpId >= NE) return;

    int s = src[warpId];
    int d = dst[warpId];
    float w0 = w[warpId * 3 + 0];
    float w1 = w[warpId * 3 + 1];
    float w2 = w[warpId * 3 + 2];

    const float* Ps  = P  + (size_t)s * HD;
    float*       out = hN + (size_t)d * HD;
#pragma unroll
    for (int j = 0; j < 2; j++) {
        int c = j * 128 + lane * 4;
        float4 p = *(const float4*)(Ps + c);
        float4 v;
        v.x = p.x + w0 * sW[c+0] + w1 * sW[HD + c+0] + w2 * sW[2*HD + c+0];
        v.y = p.y + w0 * sW[c+1] + w1 * sW[HD + c+1] + w2 * sW[2*HD + c+1];
        v.z = p.z + w0 * sW[c+2] + w1 * sW[HD + c+2] + w2 * sW[2*HD + c+2];
        v.w = p.w + w0 * sW[c+3] + w1 * sW[HD + c+3] + w2 * sW[2*HD + c+3];
        v.x = v.x > 0.0f ? v.x : 0.01f * v.x;
        v.y = v.y > 0.0f ? v.y : 0.01f * v.y;
        v.z = v.z > 0.0f ? v.z : 0.01f * v.z;
        v.w = v.w > 0.0f ? v.w : 0.01f * v.w;
        asm volatile("red.global.add.v4.f32 [%0], {%1, %2, %3, %4};"
                     :: "l"(out + c), "f"(v.x), "f"(v.y), "f"(v.z), "f"(v.w)
                     : "memory");
    }
}

// ---------------- tensor-core bf16 GEMM: packed operands + cp.async pipe ---
// C tile 128x64 = act( A1p @ B[:, :K1]^T + A2p @ B[:, K1:]^T + bias )
// Epilogue modes: fp32 C, packed Cp, or fused head dot (outv += relu(x).Wh2).
#define BM 128
#define BN 64
#define KC 32
#define RW 32   // 32-bit words per row

__global__ __launch_bounds__(256, 3)
void mma_gemm_kernel(const uint2* __restrict__ A1, int K1,
                     const uint2* __restrict__ A2, int K2,
                     const uint2* __restrict__ Bp,
                     const float* __restrict__ bias,
                     float* __restrict__ C, uint2* __restrict__ Cp,
                     const float* __restrict__ Wh2, float* __restrict__ outv,
                     int M, int N, int act) {
    __shared__ uint32_t Aw[2][BM * RW];   // 2 x 16 KB
    __shared__ uint32_t Bw[2][BN * RW];   // 2 x  8 KB

    int tid  = threadIdx.x;
    int wid  = tid >> 5;
    int lane = tid & 31;
    int grp  = lane >> 2;
    int tg   = lane & 3;
    int warp_m = wid & 3;
    int warp_n = wid >> 2;
    int m0 = warp_m * 32;
    int n0 = warp_n * 32;
    int mBase = blockIdx.y * BM;
    int nBase = blockIdx.x * BN;

    int K = K1 + K2;
    int nch = K / KC;
    int k1ch = K1 / KC;
    int kpB = K >> 1;

    uint32_t aSm[2], bSm[2];
    aSm[0] = (uint32_t)__cvta_generic_to_shared(&Aw[0][0]);
    aSm[1] = (uint32_t)__cvta_generic_to_shared(&Aw[1][0]);
    bSm[0] = (uint32_t)__cvta_generic_to_shared(&Bw[0][0]);
    bSm[1] = (uint32_t)__cvta_generic_to_shared(&Bw[1][0]);

    float acc[2][4][4];
#pragma unroll
    for (int i = 0; i < 2; i++)
#pragma unroll
        for (int j = 0; j < 4; j++)
#pragma unroll
            for (int q = 0; q < 4; q++) acc[i][j][q] = 0.0f;

    auto load_chunk = [&](int kc, int b) {
        int kp = kc * (KC / 2);
        bool u2 = (kc >= k1ch);
        const uint2* Ap = u2 ? A2 : A1;
        int kpa = u2 ? kp - (K1 >> 1) : kp;
        int lda = (u2 ? K2 : K1) >> 1;
#pragma unroll
        for (int i = 0; i < 4; i++) {
            int job = tid + i * 256;
            int r = job >> 3, s = job & 7;
            int row = mBase + r; if (row >= M) row = M - 1;
            const uint2* g = Ap + (size_t)row * lda + kpa + 2 * s;
            uint32_t d = aSm[b] + (uint32_t)(r * RW + ((4 * s) ^ ((r & 3) << 3))) * 4u;
            cp_async16(d, g);
        }
#pragma unroll
        for (int i = 0; i < 2; i++) {
            int job = tid + i * 256;
            int r = job >> 3, s = job & 7;
            const uint2* g = Bp + (size_t)(nBase + r) * kpB + kp + 2 * s;
            uint32_t d = bSm[b] + (uint32_t)(r * RW + ((4 * s) ^ ((r & 3) << 3))) * 4u;
            cp_async16(d, g);
        }
    };

    load_chunk(0, 0);
    CP_COMMIT();

    for (int kc = 0; kc < nch; kc++) {
        int b = kc & 1;
        CP_WAIT0();
        // Single barrier per chunk. It also guarantees (by per-warp program
        // order) that every warp finished computing chunk kc-1, so issuing
        // cp.async for chunk kc+1 into the other buffer below is safe.
        __syncthreads();
        if (kc + 1 < nch) { load_chunk(kc + 1, (kc + 1) & 1); CP_COMMIT(); }

        const uint32_t* A = Aw[b];
        const uint32_t* Bs = Bw[b];
#pragma unroll
        for (int ks = 0; ks < 2; ks++) {
            uint2 aF[2][4];
#pragma unroll
            for (int mt = 0; mt < 2; mt++) {
                int r = m0 + mt * 16 + grp;
                int sw = (r & 3) << 2;
                int p0 = (ks * 8 + tg) ^ sw;
                int p1 = (ks * 8 + tg + 4) ^ sw;
                aF[mt][0] = *(const uint2*)&A[r * RW + 2 * p0];
                aF[mt][1] = *(const uint2*)&A[(r + 8) * RW + 2 * p0];
                aF[mt][2] = *(const uint2*)&A[r * RW + 2 * p1];
                aF[mt][3] = *(const uint2*)&A[(r + 8) * RW + 2 * p1];
            }
            uint2 bF[4][2];
#pragma unroll
            for (int nt = 0; nt < 4; nt++) {
                int nr = n0 + nt * 8 + grp;
                int sw = (nr & 3) << 2;
                bF[nt][0] = *(const uint2*)&Bs[nr * RW + 2 * ((ks * 8 + tg) ^ sw)];
                bF[nt][1] = *(const uint2*)&Bs[nr * RW + 2 * ((ks * 8 + tg + 4) ^ sw)];
            }
#pragma unroll
            for (int mt = 0; mt < 2; mt++)
#pragma unroll
                for (int nt = 0; nt < 4; nt++) {
                    float* c = acc[mt][nt];
                    mma_bf16(c, aF[mt][0].x, aF[mt][1].x, aF[mt][2].x, aF[mt][3].x,
                             bF[nt][0].x, bF[nt][1].x);
                    mma_bf16(c, aF[mt][0].y, aF[mt][1].y, aF[mt][2].y, aF[mt][3].y,
                             bF[nt][0].x, bF[nt][1].x);
                    mma_bf16(c, aF[mt][0].x, aF[mt][1].x, aF[mt][2].x, aF[mt][3].x,
                             bF[nt][0].y, bF[nt][1].y);
                }
        }
    }

    // Epilogue
#pragma unroll
    for (int mt = 0; mt < 2; mt++) {
#pragma unroll
        for (int half = 0; half < 2; half++) {
            int row = mBase + m0 + mt * 16 + grp + half * 8;
            float part = 0.0f;
#pragma unroll
            for (int nt = 0; nt < 4; nt++) {
                int col = nBase + n0 + nt * 8 + 2 * tg;
                float2 v;
                v.x = acc[mt][nt][half * 2 + 0];
                v.y = acc[mt][nt][half * 2 + 1];
                if (bias) { v.x += bias[col]; v.y += bias[col + 1]; }
                if (act)  { v.x = fmaxf(v.x, 0.0f); v.y = fmaxf(v.y, 0.0f); }
                if (outv) {
                    part += v.x * Wh2[col] + v.y * Wh2[col + 1];
                } else if (row < M) {
                    if (Cp) {
                        uint32_t hi, lo;
                        split2(v.x, v.y, hi, lo);
                        Cp[(size_t)row * (N >> 1) + (col >> 1)] = make_uint2(hi, lo);
                    } else {
                        *(float2*)(C + (size_t)row * N + col) = v;
                    }
                }
            }
            if (outv) {
                // reduce across the 4 tg lanes of this quad (lanes 4g..4g+3)
                part += __shfl_xor_sync(0xffffffffu, part, 1);
                part += __shfl_xor_sync(0xffffffffu, part, 2);
                if (tg == 0 && row < M) atomicAdd(&outv[row], part);
            }
        }
    }
}

// ---------------- launch ---------------------------------------------------
extern "C" void kernel_launch(void* const* d_in, const int* in_sizes, int n_in,
                              void* d_out, int out_size) {
    const int*   gate_type = (const int*)  d_in[0];
    const int*   src       = (const int*)  d_in[1];
    const int*   dst       = (const int*)  d_in[2];
    const float* w         = (const float*)d_in[3];
    const float* emb       = (const float*)d_in[4];
    const float* W1        = (const float*)d_in[5];
    const float* W2        = (const float*)d_in[6];
    const float* b2        = (const float*)d_in[7];
    const float* Wh1       = (const float*)d_in[8];
    const float* bh1       = (const float*)d_in[9];
    const float* Wh2       = (const float*)d_in[10];
    const float* bh2       = (const float*)d_in[11];
    float* out = (float*)d_out;

    float *P, *hN, *deg, *invdeg;
    uint2 *hPkA, *hPkB, *hNp, *W1p, *W2p, *Wh1p;
    cudaGetSymbolAddress((void**)&P,      g_P);
    cudaGetSymbolAddress((void**)&hN,     g_hN);
    cudaGetSymbolAddress((void**)&deg,    g_deg);
    cudaGetSymbolAddress((void**)&invdeg, g_invdeg);
    cudaGetSymbolAddress((void**)&hPkA,   g_hPkA);
    cudaGetSymbolAddress((void**)&hPkB,   g_hPkB);
    cudaGetSymbolAddress((void**)&hNp,    g_hNp);
    cudaGetSymbolAddress((void**)&W1p,    g_W1p);
    cudaGetSymbolAddress((void**)&W2p,    g_W2p);
    cudaGetSymbolAddress((void**)&Wh1p,   g_Wh1p);

    // h0 packed; deg=0; out=bh2
    init_kernel<<<(NN * HP + 255) / 256, 256>>>(gate_type, emb, hPkA, deg, out, bh2);
    deg_kernel<<<(NE + 255) / 256, 256>>>(dst, deg);
    invdeg_kernel<<<(NN + 255) / 256, 256>>>(deg, invdeg);

    // pack weights (once per launch)
    for (int l = 0; l < NL; l++) {
        pack_kernel<<<(256 * 128 + 255) / 256, 256>>>(
            (float*)(W1 + (size_t)l * HD * W1_LD), W1_LD, 128, 256 * 128, nullptr,
            W1p + (size_t)l * 256 * 128, 0);
        pack_kernel<<<(256 * 256 + 255) / 256, 256>>>(
            (float*)(W2 + (size_t)l * HD * W2_LD), W2_LD, 256, 256 * 256, nullptr,
            W2p + (size_t)l * 256 * 256, 0);
    }
    pack_kernel<<<(256 * 128 + 255) / 256, 256>>>(
        (float*)Wh1, HD, 128, 256 * 128, nullptr, Wh1p, 0);

    // hN zero for the first layer (subsequent layers zeroed by fused pack)
    zero_kernel<<<2048, 256>>>((float4*)hN, NN * HD / 4);

    dim3 ggrid(HD / BN, (NN + BM - 1) / BM);   // (4, 782)
    uint2* hcur = hPkA;
    uint2* hnext = hPkB;

    for (int l = 0; l < NL; l++) {
        const float* W1l = W1 + (size_t)l * HD * W1_LD;
        const float* b2l = b2 + (size_t)l * HD;

        // P = h @ W1[:, :256]^T  (fp32 out, consumed by edge scatter)
        mma_gemm_kernel<<<ggrid, 256>>>(hcur, HD, nullptr, 0,
                                        W1p + (size_t)l * 256 * 128,
                                        nullptr, P, nullptr, nullptr, nullptr,
                                        NN, HD, 0);

        // hN[dst] += leaky_relu(P[src] + w @ W1[:, 256:259]^T)
        edge_kernel<<<(NE * 32 + 255) / 256, 256>>>(src, dst, w, P, W1l + HD, hN);

        // hNp = pack(hN * invdeg); also zeroes hN for the next layer
        pack_kernel<<<(NN * HP + 255) / 256, 256>>>(hN, HD, HP, NN * HP, invdeg,
                                                    hNp, 1);

        // h' = relu([h | hN*invdeg] @ W2^T + b2)  -> packed
        mma_gemm_kernel<<<ggrid, 256>>>(hcur, HD, hNp, HD,
                                        W2p + (size_t)l * 256 * 256,
                                        b2l, nullptr, hnext, nullptr, nullptr,
                                        NN, HD, 1);

        uint2* t = hcur; hcur = hnext; hnext = t;
    }

    // head fused: out[n] = bh2 + sum_c relu(h @ Wh1^T + bh1)[n,c] * Wh2[c]
    mma_gemm_kernel<<<ggrid, 256>>>(hcur, HD, nullptr, 0, Wh1p,
                                    bh1, nullptr, nullptr, Wh2, out,
                                    NN, HD, 1);
}

// round 15
// speedup vs baseline: 1.4405x; 1.0984x over previous
#include <cuda_runtime.h>
#include <cuda_bf16.h>
#include <cstdint>
#include <cstddef>

// Problem constants
#define NN 100000      // nodes
#define NE 800000      // edges
#define HD 256         // hidden dim
#define NL 6           // layers
#define W1_LD 259      // H + 3 edge features
#define W2_LD 512      // H + INTER
#define HP 128         // packed pairs per node row (HD/2)

// ---------------- scratch (device globals; no runtime allocation) ----------
__device__ float g_P [(size_t)NN * HD];
__device__ uint2 g_hPkA[(size_t)NN * HP];
__device__ uint2 g_hPkB[(size_t)NN * HP];
__device__ uint2 g_hNp [(size_t)NN * HP];
__device__ uint2 g_W1p [NL * 256 * 128];
__device__ uint2 g_W2p [NL * 256 * 256];
__device__ uint2 g_Wh1p[256 * 128];
__device__ int   g_offs[NN + 1];
__device__ int   g_cursor[NN];
__device__ int   g_eidx[NE];
__device__ int   g_bsum[512];

// split a,b into bf16 (hi, lo) packed words
__device__ __forceinline__ void split2(float a, float b, uint32_t& hi, uint32_t& lo) {
    __nv_bfloat16 ha = __float2bfloat16(a);
    __nv_bfloat16 hb = __float2bfloat16(b);
    __nv_bfloat16 la = __float2bfloat16(a - __bfloat162float(ha));
    __nv_bfloat16 lb = __float2bfloat16(b - __bfloat162float(hb));
    __nv_bfloat162 h2 = __halves2bfloat162(ha, hb);
    __nv_bfloat162 l2 = __halves2bfloat162(la, lb);
    hi = *reinterpret_cast<uint32_t*>(&h2);
    lo = *reinterpret_cast<uint32_t*>(&l2);
}

__device__ __forceinline__ void mma_bf16(float* c,
                                         uint32_t a0, uint32_t a1, uint32_t a2, uint32_t a3,
                                         uint32_t b0, uint32_t b1) {
    asm volatile(
        "mma.sync.aligned.m16n8k16.row.col.f32.bf16.bf16.f32 "
        "{%0,%1,%2,%3}, {%4,%5,%6,%7}, {%8,%9}, {%0,%1,%2,%3};"
        : "+f"(c[0]), "+f"(c[1]), "+f"(c[2]), "+f"(c[3])
        : "r"(a0), "r"(a1), "r"(a2), "r"(a3), "r"(b0), "r"(b1));
}

__device__ __forceinline__ void cp_async16(uint32_t smem_dst, const void* gsrc) {
    asm volatile("cp.async.cg.shared.global [%0], [%1], 16;"
                 :: "r"(smem_dst), "l"(gsrc) : "memory");
}
#define CP_COMMIT() asm volatile("cp.async.commit_group;" ::: "memory")
#define CP_WAIT0()  asm volatile("cp.async.wait_group 0;" ::: "memory")

// ---------------- setup kernels --------------------------------------------
__global__ void init_kernel(const int* __restrict__ gt,
                            const float* __restrict__ emb,
                            uint2* __restrict__ hp,
                            float* __restrict__ outv,
                            const float* __restrict__ bh2) {
    int i = blockIdx.x * blockDim.x + threadIdx.x;
    if (i < NN * HP) {
        int node = i >> 7;
        int j    = i & 127;
        const float* e = emb + gt[node] * HD + 2 * j;
        uint32_t hi, lo;
        split2(e[0], e[1], hi, lo);
        hp[i] = make_uint2(hi, lo);
    }
    if (i < NN) outv[i] = bh2[0];     // out pre-initialized for fused head dot
}

__global__ void zero_int(int* __restrict__ p, int n) {
    int i = blockIdx.x * blockDim.x + threadIdx.x;
    if (i < n) p[i] = 0;
}

__global__ void count_kernel(const int* __restrict__ dst, int* __restrict__ ideg) {
    int e = blockIdx.x * blockDim.x + threadIdx.x;
    if (e < NE) atomicAdd(&ideg[dst[e]], 1);
}

#define SB 512
__global__ void scan_block(const int* __restrict__ in, int* __restrict__ outEx,
                           int* __restrict__ bsum, int n) {
    __shared__ int s[SB];
    int i = blockIdx.x * SB + threadIdx.x;
    int v = (i < n) ? in[i] : 0;
    s[threadIdx.x] = v;
    __syncthreads();
    for (int d = 1; d < SB; d <<= 1) {
        int t = (threadIdx.x >= (unsigned)d) ? s[threadIdx.x - d] : 0;
        __syncthreads();
        s[threadIdx.x] += t;
        __syncthreads();
    }
    if (i < n) outEx[i] = s[threadIdx.x] - v;
    if (threadIdx.x == SB - 1) bsum[blockIdx.x] = s[SB - 1];
}

__global__ void scan_tops(int* __restrict__ bsum, int nb) {
    __shared__ int s[SB];
    int v = (threadIdx.x < (unsigned)nb) ? bsum[threadIdx.x] : 0;
    s[threadIdx.x] = v;
    __syncthreads();
    for (int d = 1; d < SB; d <<= 1) {
        int t = (threadIdx.x >= (unsigned)d) ? s[threadIdx.x - d] : 0;
        __syncthreads();
        s[threadIdx.x] += t;
        __syncthreads();
    }
    if (threadIdx.x < (unsigned)nb) bsum[threadIdx.x] = s[threadIdx.x] - v;
}

__global__ void scan_add(int* __restrict__ outEx, const int* __restrict__ bsum,
                         int* __restrict__ cursor, int n) {
    int i = blockIdx.x * blockDim.x + threadIdx.x;
    if (i < n) {
        int v = outEx[i] + bsum[i / SB];
        outEx[i] = v;
        cursor[i] = v;
    }
    if (i == 0) outEx[n] = NE;
}

__global__ void fill_kernel(const int* __restrict__ dst, int* __restrict__ cursor,
                            int* __restrict__ eidx) {
    int e = blockIdx.x * blockDim.x + threadIdx.x;
    if (e < NE) {
        int pos = atomicAdd(&cursor[dst[e]], 1);
        eidx[pos] = e;
    }
}

// pack fp32 [rows, srcld] -> uint2 hi/lo [rows, kp] (weights only)
__global__ void pack_kernel(const float* __restrict__ src, int srcld, int kp,
                            int total, uint2* __restrict__ dst) {
    int i = blockIdx.x * blockDim.x + threadIdx.x;
    if (i >= total) return;
    int r = i / kp, j = i - r * kp;
    float a = src[(size_t)r * srcld + 2 * j];
    float b = src[(size_t)r * srcld + 2 * j + 1];
    uint32_t hi, lo;
    split2(a, b, hi, lo);
    dst[(size_t)r * kp + j] = make_uint2(hi, lo);
}

// ---------------- CSR gather (4-edge unrolled, 2 warps/node) ----------------
// hNp[n] = pack( (1/max(deg,1)) * sum_e leaky_relu(P[src_e] + w_e @ W1b^T) )
__global__ __launch_bounds__(256)
void csr_gather_kernel(const int* __restrict__ offs,
                       const int* __restrict__ eidx,
                       const int* __restrict__ src,
                       const float* __restrict__ w,
                       const float* __restrict__ P,
                       const float* __restrict__ W1b,
                       uint2* __restrict__ hNp) {
    __shared__ float sW[3 * HD];
    for (int i = threadIdx.x; i < HD; i += blockDim.x) {
        sW[i]          = W1b[(size_t)i * W1_LD + 0];
        sW[HD + i]     = W1b[(size_t)i * W1_LD + 1];
        sW[2 * HD + i] = W1b[(size_t)i * W1_LD + 2];
    }
    __syncthreads();

    int gw = blockIdx.x * 8 + (threadIdx.x >> 5);   // global warp id
    int lane = threadIdx.x & 31;
    if (gw >= NN * 2) return;
    int node = gw >> 1;
    int half = gw & 1;
    int c = half * 128 + lane * 4;

    float wa0 = sW[c],        wa1 = sW[c+1],        wa2 = sW[c+2],        wa3 = sW[c+3];
    float wb0 = sW[HD+c],     wb1 = sW[HD+c+1],     wb2 = sW[HD+c+2],     wb3 = sW[HD+c+3];
    float wc0 = sW[2*HD+c],   wc1 = sW[2*HD+c+1],   wc2 = sW[2*HD+c+2],   wc3 = sW[2*HD+c+3];

    int beg = offs[node], end = offs[node + 1];
    float a0 = 0.f, a1 = 0.f, a2 = 0.f, a3 = 0.f;

    for (int e = beg; e < end; e += 4) {
        int last = end - 1;
        int i1 = e + 1 <= last ? e + 1 : last;
        int i2 = e + 2 <= last ? e + 2 : last;
        int i3 = e + 3 <= last ? e + 3 : last;
        float m1 = e + 1 < end ? 1.f : 0.f;
        float m2 = e + 2 < end ? 1.f : 0.f;
        float m3 = e + 3 < end ? 1.f : 0.f;

        int ed0 = eidx[e],  ed1 = eidx[i1], ed2 = eidx[i2], ed3 = eidx[i3];
        int s0 = src[ed0], s1 = src[ed1], s2 = src[ed2], s3 = src[ed3];
        float e00 = w[ed0*3], e01 = w[ed0*3+1], e02 = w[ed0*3+2];
        float e10 = w[ed1*3], e11 = w[ed1*3+1], e12 = w[ed1*3+2];
        float e20 = w[ed2*3], e21 = w[ed2*3+1], e22 = w[ed2*3+2];
        float e30 = w[ed3*3], e31 = w[ed3*3+1], e32 = w[ed3*3+2];
        float4 p0 = *(const float4*)(P + (size_t)s0 * HD + c);
        float4 p1 = *(const float4*)(P + (size_t)s1 * HD + c);
        float4 p2 = *(const float4*)(P + (size_t)s2 * HD + c);
        float4 p3 = *(const float4*)(P + (size_t)s3 * HD + c);

        float t;
        t = p0.x + e00*wa0 + e01*wb0 + e02*wc0; a0 +=      (t > 0.f ? t : 0.01f*t);
        t = p0.y + e00*wa1 + e01*wb1 + e02*wc1; a1 +=      (t > 0.f ? t : 0.01f*t);
        t = p0.z + e00*wa2 + e01*wb2 + e02*wc2; a2 +=      (t > 0.f ? t : 0.01f*t);
        t = p0.w + e00*wa3 + e01*wb3 + e02*wc3; a3 +=      (t > 0.f ? t : 0.01f*t);
        t = p1.x + e10*wa0 + e11*wb0 + e12*wc0; a0 += m1 * (t > 0.f ? t : 0.01f*t);
        t = p1.y + e10*wa1 + e11*wb1 + e12*wc1; a1 += m1 * (t > 0.f ? t : 0.01f*t);
        t = p1.z + e10*wa2 + e11*wb2 + e12*wc2; a2 += m1 * (t > 0.f ? t : 0.01f*t);
        t = p1.w + e10*wa3 + e11*wb3 + e12*wc3; a3 += m1 * (t > 0.f ? t : 0.01f*t);
        t = p2.x + e20*wa0 + e21*wb0 + e22*wc0; a0 += m2 * (t > 0.f ? t : 0.01f*t);
        t = p2.y + e20*wa1 + e21*wb1 + e22*wc1; a1 += m2 * (t > 0.f ? t : 0.01f*t);
        t = p2.z + e20*wa2 + e21*wb2 + e22*wc2; a2 += m2 * (t > 0.f ? t : 0.01f*t);
        t = p2.w + e20*wa3 + e21*wb3 + e22*wc3; a3 += m2 * (t > 0.f ? t : 0.01f*t);
        t = p3.x + e30*wa0 + e31*wb0 + e32*wc0; a0 += m3 * (t > 0.f ? t : 0.01f*t);
        t = p3.y + e30*wa1 + e31*wb1 + e32*wc1; a1 += m3 * (t > 0.f ? t : 0.01f*t);
        t = p3.z + e30*wa2 + e31*wb2 + e32*wc2; a2 += m3 * (t > 0.f ? t : 0.01f*t);
        t = p3.w + e30*wa3 + e31*wb3 + e32*wc3; a3 += m3 * (t > 0.f ? t : 0.01f*t);
    }

    float inv = 1.0f / fmaxf((float)(end - beg), 1.0f);
    a0 *= inv; a1 *= inv; a2 *= inv; a3 *= inv;

    uint32_t hi, lo;
    uint2* outp = hNp + (size_t)node * HP + half * 64 + lane * 2;
    split2(a0, a1, hi, lo); outp[0] = make_uint2(hi, lo);
    split2(a2, a3, hi, lo); outp[1] = make_uint2(hi, lo);
}

// ---------------- tensor-core bf16 GEMM: packed operands + cp.async pipe ---
#define BM 128
#define BN 64
#define KC 32
#define RW 32   // 32-bit words per row

__global__ __launch_bounds__(256, 3)
void mma_gemm_kernel(const uint2* __restrict__ A1, int K1,
                     const uint2* __restrict__ A2, int K2,
                     const uint2* __restrict__ Bp,
                     const float* __restrict__ bias,
                     float* __restrict__ C, uint2* __restrict__ Cp,
                     const float* __restrict__ Wh2, float* __restrict__ outv,
                     int M, int N, int act) {
    __shared__ uint32_t Aw[2][BM * RW];   // 2 x 16 KB
    __shared__ uint32_t Bw[2][BN * RW];   // 2 x  8 KB

    int tid  = threadIdx.x;
    int wid  = tid >> 5;
    int lane = tid & 31;
    int grp  = lane >> 2;
    int tg   = lane & 3;
    int warp_m = wid & 3;
    int warp_n = wid >> 2;
    int m0 = warp_m * 32;
    int n0 = warp_n * 32;
    int mBase = blockIdx.y * BM;
    int nBase = blockIdx.x * BN;

    int K = K1 + K2;
    int nch = K / KC;
    int k1ch = K1 / KC;
    int kpB = K >> 1;

    uint32_t aSm[2], bSm[2];
    aSm[0] = (uint32_t)__cvta_generic_to_shared(&Aw[0][0]);
    aSm[1] = (uint32_t)__cvta_generic_to_shared(&Aw[1][0]);
    bSm[0] = (uint32_t)__cvta_generic_to_shared(&Bw[0][0]);
    bSm[1] = (uint32_t)__cvta_generic_to_shared(&Bw[1][0]);

    float acc[2][4][4];
#pragma unroll
    for (int i = 0; i < 2; i++)
#pragma unroll
        for (int j = 0; j < 4; j++)
#pragma unroll
            for (int q = 0; q < 4; q++) acc[i][j][q] = 0.0f;

    auto load_chunk = [&](int kc, int b) {
        int kp = kc * (KC / 2);
        bool u2 = (kc >= k1ch);
        const uint2* Ap = u2 ? A2 : A1;
        int kpa = u2 ? kp - (K1 >> 1) : kp;
        int lda = (u2 ? K2 : K1) >> 1;
#pragma unroll
        for (int i = 0; i < 4; i++) {
            int job = tid + i * 256;
            int r = job >> 3, s = job & 7;
            int row = mBase + r; if (row >= M) row = M - 1;
            const uint2* g = Ap + (size_t)row * lda + kpa + 2 * s;
            uint32_t d = aSm[b] + (uint32_t)(r * RW + ((4 * s) ^ ((r & 3) << 3))) * 4u;
            cp_async16(d, g);
        }
#pragma unroll
        for (int i = 0; i < 2; i++) {
            int job = tid + i * 256;
            int r = job >> 3, s = job & 7;
            const uint2* g = Bp + (size_t)(nBase + r) * kpB + kp + 2 * s;
            uint32_t d = bSm[b] + (uint32_t)(r * RW + ((4 * s) ^ ((r & 3) << 3))) * 4u;
            cp_async16(d, g);
        }
    };

    load_chunk(0, 0);
    CP_COMMIT();

    for (int kc = 0; kc < nch; kc++) {
        int b = kc & 1;
        CP_WAIT0();
        // Single barrier per chunk: also guarantees (by per-warp program
        // order) everyone finished computing chunk kc-1 before the buffer
        // below is overwritten.
        __syncthreads();
        if (kc + 1 < nch) { load_chunk(kc + 1, (kc + 1) & 1); CP_COMMIT(); }

        const uint32_t* A = Aw[b];
        const uint32_t* Bs = Bw[b];
#pragma unroll
        for (int ks = 0; ks < 2; ks++) {
            uint2 aF[2][4];
#pragma unroll
            for (int mt = 0; mt < 2; mt++) {
                int r = m0 + mt * 16 + grp;
                int sw = (r & 3) << 2;
                int p0 = (ks * 8 + tg) ^ sw;
                int p1 = (ks * 8 + tg + 4) ^ sw;
                aF[mt][0] = *(const uint2*)&A[r * RW + 2 * p0];
                aF[mt][1] = *(const uint2*)&A[(r + 8) * RW + 2 * p0];
                aF[mt][2] = *(const uint2*)&A[r * RW + 2 * p1];
                aF[mt][3] = *(const uint2*)&A[(r + 8) * RW + 2 * p1];
            }
            uint2 bF[4][2];
#pragma unroll
            for (int nt = 0; nt < 4; nt++) {
                int nr = n0 + nt * 8 + grp;
                int sw = (nr & 3) << 2;
                bF[nt][0] = *(const uint2*)&Bs[nr * RW + 2 * ((ks * 8 + tg) ^ sw)];
                bF[nt][1] = *(const uint2*)&Bs[nr * RW + 2 * ((ks * 8 + tg + 4) ^ sw)];
            }
#pragma unroll
            for (int mt = 0; mt < 2; mt++)
#pragma unroll
                for (int nt = 0; nt < 4; nt++) {
                    float* c = acc[mt][nt];
                    mma_bf16(c, aF[mt][0].x, aF[mt][1].x, aF[mt][2].x, aF[mt][3].x,
                             bF[nt][0].x, bF[nt][1].x);
                    mma_bf16(c, aF[mt][0].y, aF[mt][1].y, aF[mt][2].y, aF[mt][3].y,
                             bF[nt][0].x, bF[nt][1].x);
                    mma_bf16(c, aF[mt][0].x, aF[mt][1].x, aF[mt][2].x, aF[mt][3].x,
                             bF[nt][0].y, bF[nt][1].y);
                }
        }
    }

    // Epilogue
#pragma unroll
    for (int mt = 0; mt < 2; mt++) {
#pragma unroll
        for (int half = 0; half < 2; half++) {
            int row = mBase + m0 + mt * 16 + grp + half * 8;
            float part = 0.0f;
#pragma unroll
            for (int nt = 0; nt < 4; nt++) {
                int col = nBase + n0 + nt * 8 + 2 * tg;
                float2 v;
                v.x = acc[mt][nt][half * 2 + 0];
                v.y = acc[mt][nt][half * 2 + 1];
                if (bias) { v.x += bias[col]; v.y += bias[col + 1]; }
                if (act)  { v.x = fmaxf(v.x, 0.0f); v.y = fmaxf(v.y, 0.0f); }
                if (outv) {
                    part += v.x * Wh2[col] + v.y * Wh2[col + 1];
                } else if (row < M) {
                    if (Cp) {
                        uint32_t hi, lo;
                        split2(v.x, v.y, hi, lo);
                        Cp[(size_t)row * (N >> 1) + (col >> 1)] = make_uint2(hi, lo);
                    } else {
                        *(float2*)(C + (size_t)row * N + col) = v;
                    }
                }
            }
            if (outv) {
                part += __shfl_xor_sync(0xffffffffu, part, 1);
                part += __shfl_xor_sync(0xffffffffu, part, 2);
                if (tg == 0 && row < M) atomicAdd(&outv[row], part);
            }
        }
    }
}

// ---------------- launch ---------------------------------------------------
extern "C" void kernel_launch(void* const* d_in, const int* in_sizes, int n_in,
                              void* d_out, int out_size) {
    const int*   gate_type = (const int*)  d_in[0];
    const int*   src       = (const int*)  d_in[1];
    const int*   dst       = (const int*)  d_in[2];
    const float* w         = (const float*)d_in[3];
    const float* emb       = (const float*)d_in[4];
    const float* W1        = (const float*)d_in[5];
    const float* W2        = (const float*)d_in[6];
    const float* b2        = (const float*)d_in[7];
    const float* Wh1       = (const float*)d_in[8];
    const float* bh1       = (const float*)d_in[9];
    const float* Wh2       = (const float*)d_in[10];
    const float* bh2       = (const float*)d_in[11];
    float* out = (float*)d_out;

    float *P;
    uint2 *hPkA, *hPkB, *hNp, *W1p, *W2p, *Wh1p;
    int *offs, *cursor, *eidx, *bsum;
    cudaGetSymbolAddress((void**)&P,      g_P);
    cudaGetSymbolAddress((void**)&hPkA,   g_hPkA);
    cudaGetSymbolAddress((void**)&hPkB,   g_hPkB);
    cudaGetSymbolAddress((void**)&hNp,    g_hNp);
    cudaGetSymbolAddress((void**)&W1p,    g_W1p);
    cudaGetSymbolAddress((void**)&W2p,    g_W2p);
    cudaGetSymbolAddress((void**)&Wh1p,   g_Wh1p);
    cudaGetSymbolAddress((void**)&offs,   g_offs);
    cudaGetSymbolAddress((void**)&cursor, g_cursor);
    cudaGetSymbolAddress((void**)&eidx,   g_eidx);
    cudaGetSymbolAddress((void**)&bsum,   g_bsum);

    // h0 packed; out = bh2 (fused head)
    init_kernel<<<(NN * HP + 255) / 256, 256>>>(gate_type, emb, hPkA, out, bh2);

    // CSR build (graph static across layers)
    int nb = (NN + SB - 1) / SB;   // 196
    zero_int<<<(NN + 255) / 256, 256>>>(cursor, NN);
    count_kernel<<<(NE + 255) / 256, 256>>>(dst, cursor);
    scan_block<<<nb, SB>>>(cursor, offs, bsum, NN);
    scan_tops<<<1, SB>>>(bsum, nb);
    scan_add<<<(NN + 255) / 256, 256>>>(offs, bsum, cursor, NN);
    fill_kernel<<<(NE + 255) / 256, 256>>>(dst, cursor, eidx);

    // pack weights (once per launch)
    for (int l = 0; l < NL; l++) {
        pack_kernel<<<(256 * 128 + 255) / 256, 256>>>(
            W1 + (size_t)l * HD * W1_LD, W1_LD, 128, 256 * 128,
            W1p + (size_t)l * 256 * 128);
        pack_kernel<<<(256 * 256 + 255) / 256, 256>>>(
            W2 + (size_t)l * HD * W2_LD, W2_LD, 256, 256 * 256,
            W2p + (size_t)l * 256 * 256);
    }
    pack_kernel<<<(256 * 128 + 255) / 256, 256>>>(Wh1, HD, 128, 256 * 128, Wh1p);

    dim3 ggrid(HD / BN, (NN + BM - 1) / BM);   // (4, 782)
    uint2* hcur = hPkA;
    uint2* hnext = hPkB;

    for (int l = 0; l < NL; l++) {
        const float* W1l = W1 + (size_t)l * HD * W1_LD;
        const float* b2l = b2 + (size_t)l * HD;

        // P = h @ W1[:, :256]^T  (fp32 out, consumed by gather)
        mma_gemm_kernel<<<ggrid, 256>>>(hcur, HD, nullptr, 0,
                                        W1p + (size_t)l * 256 * 128,
                                        nullptr, P, nullptr, nullptr, nullptr,
                                        NN, HD, 0);

        // hNp[n] = pack(mean_e leaky(P[src] + w@W1b^T))  (gather, no atomics)
        csr_gather_kernel<<<(NN * 2 + 7) / 8, 256>>>(offs, eidx, src, w, P,
                                                     W1l + HD, hNp);

        // h' = relu([h | hNp] @ W2^T + b2) -> packed
        mma_gemm_kernel<<<ggrid, 256>>>(hcur, HD, hNp, HD,
                                        W2p + (size_t)l * 256 * 256,
                                        b2l, nullptr, hnext, nullptr, nullptr,
                                        NN, HD, 1);

        uint2* t = hcur; hcur = hnext; hnext = t;
    }

    // head fused: out[n] = bh2 + sum_c relu(h @ Wh1^T + bh1)[n,c] * Wh2[c]
    mma_gemm_kernel<<<ggrid, 256>>>(hcur, HD, nullptr, 0, Wh1p,
                                    bh1, nullptr, nullptr, Wh2, out,
                                    NN, HD, 1);
}